// round 1
// baseline (speedup 1.0000x reference)
#include <cuda_runtime.h>
#include <cuda_bf16.h>

// Problem constants
#define Hd 256
#define Wd 256
#define HWn 65536
#define Bn 4
#define Dn 5
#define Cn 3
#define Sn 27

// Output layout in d_out (flattened tuple: res_i, out, samples)
#define RES_OFF  0L
#define OUT_OFF  (4L*3*3*HWn)               // 2359296
#define SAMP_OFF (OUT_OFF + 4L*3*HWn)       // 3145728
// total = 24379392

// Scratch (device globals; no runtime allocation allowed)
__device__ float g_f1[4L*64*HWn];    // f1 (64ch) ; reused for h2
__device__ float g_feat[4L*128*HWn]; // feature (128ch)
__device__ float g_off[4L*81*HWn];   // offsets (81ch)
__device__ float g_h1[4L*64*HWn];    // h1 (64ch)
__device__ float g_wt[4L*27*HWn];    // weights (27ch)

// ---------------------------------------------------------------------------
// Generic 3x3 SAME conv, stride 1. Input channels may come from up to 3
// concatenated sources. Block: 256 threads, 32x32 output tile, 8 out-channels.
// Each thread: 4 pixels (vertical) x 8 out-channels in registers.
// ---------------------------------------------------------------------------
template<bool RELU>
__global__ void __launch_bounds__(256)
conv3x3_k(const float* __restrict__ s0, int c0, long bs0,
          const float* __restrict__ s1, int c1, long bs1,
          const float* __restrict__ s2, long bs2,
          const float* __restrict__ wgt, const float* __restrict__ bias,
          float* __restrict__ dst, int CIN, int COUT)
{
    const int tid = threadIdx.x;
    const int tx = tid & 31;
    const int ty = tid >> 5;            // 0..7
    const int tilex = blockIdx.x * 32;
    const int tiley = blockIdx.y * 32;
    const int nchunk = (COUT + 7) >> 3;
    const int b   = blockIdx.z / nchunk;
    const int ocb = (blockIdx.z % nchunk) * 8;

    __shared__ float tile[34 * 34];
    __shared__ float wsm[72];

    float acc[4][8];
#pragma unroll
    for (int p = 0; p < 4; p++)
#pragma unroll
        for (int o = 0; o < 8; o++) acc[p][o] = 0.f;

    for (int cin = 0; cin < CIN; ++cin) {
        const float* src;
        if (cin < c0)       src = s0 + b * bs0 + (long)cin * HWn;
        else if (cin < c1)  src = s1 + b * bs1 + (long)(cin - c0) * HWn;
        else                src = s2 + b * bs2 + (long)(cin - c1) * HWn;

        // weights for this input channel, 8 out-channels
        if (tid < 72) {
            int oc = ocb + tid / 9;
            wsm[tid] = (oc < COUT) ? wgt[((long)oc * CIN + cin) * 9 + tid % 9] : 0.f;
        }
        // 34x34 halo tile (zero padding outside)
#pragma unroll 2
        for (int i = tid; i < 34 * 34; i += 256) {
            int r = i / 34, c = i - r * 34;
            int gh = tiley - 1 + r, gw = tilex - 1 + c;
            float v = 0.f;
            if ((unsigned)gh < (unsigned)Hd && (unsigned)gw < (unsigned)Wd)
                v = src[gh * Wd + gw];
            tile[i] = v;
        }
        __syncthreads();

        float in[6][3];
#pragma unroll
        for (int i = 0; i < 6; i++)
#pragma unroll
            for (int j = 0; j < 3; j++)
                in[i][j] = tile[(ty * 4 + i) * 34 + tx + j];

#pragma unroll
        for (int o = 0; o < 8; o++) {
            float w[9];
#pragma unroll
            for (int k = 0; k < 9; k++) w[k] = wsm[o * 9 + k];
#pragma unroll
            for (int p = 0; p < 4; p++) {
                float s = acc[p][o];
#pragma unroll
                for (int kh = 0; kh < 3; kh++)
#pragma unroll
                    for (int kw = 0; kw < 3; kw++)
                        s += in[p + kh][kw] * w[kh * 3 + kw];
                acc[p][o] = s;
            }
        }
        __syncthreads();
    }

#pragma unroll
    for (int o = 0; o < 8; o++) {
        int oc = ocb + o;
        if (oc >= COUT) break;
        float bv = bias[oc];
#pragma unroll
        for (int p = 0; p < 4; p++) {
            float v = acc[p][o] + bv;
            if (RELU) v = fmaxf(v, 0.f);
            dst[((long)b * COUT + oc) * HWn + (tiley + ty * 4 + p) * Wd + tilex + tx] = v;
        }
    }
}

// ---------------------------------------------------------------------------
// Trilinear deformable sampling: data[B,D,C,H,W], offsets[B,S*3,H,W]
// -> samples[B,S,C,H,W]
// ---------------------------------------------------------------------------
__global__ void trilerp_k(const float* __restrict__ data,
                          const float* __restrict__ off,
                          float* __restrict__ samp)
{
    long idx = blockIdx.x * 256L + threadIdx.x;      // over B*S*HW
    if (idx >= (long)Bn * Sn * HWn) return;
    int hw = (int)(idx % HWn);
    int s  = (int)((idx / HWn) % Sn);
    int b  = (int)(idx / ((long)Sn * HWn));
    int h = hw >> 8, w = hw & 255;

    int kd = s / 9 - 1;
    int kh = (s / 3) % 3 - 1;
    int kw = s % 3 - 1;

    const float* ob = off + ((long)b * (Sn * 3) + s * 3) * HWn + hw;
    float pd = 2.0f + (float)kd + ob[0];
    float ph = (float)h + (float)kh + ob[HWn];
    float pw = (float)w + (float)kw + ob[2L * HWn];
    pd = fminf(fmaxf(pd, 0.f), (float)(Dn - 1));
    ph = fminf(fmaxf(ph, 0.f), (float)(Hd - 1));
    pw = fminf(fmaxf(pw, 0.f), (float)(Wd - 1));

    float d0f = floorf(pd), h0f = floorf(ph), w0f = floorf(pw);
    float fd = pd - d0f, fh = ph - h0f, fw = pw - w0f;
    int d0 = (int)d0f, h0 = (int)h0f, w0 = (int)w0f;
    int d1 = min(d0 + 1, Dn - 1);
    int h1 = min(h0 + 1, Hd - 1);
    int w1 = min(w0 + 1, Wd - 1);

    float gd0 = 1.f - fd, gh0 = 1.f - fh, gw0 = 1.f - fw;
    float w000 = gd0 * gh0 * gw0, w001 = gd0 * gh0 * fw;
    float w010 = gd0 * fh  * gw0, w011 = gd0 * fh  * fw;
    float w100 = fd  * gh0 * gw0, w101 = fd  * gh0 * fw;
    float w110 = fd  * fh  * gw0, w111 = fd  * fh  * fw;

    long i00 = (long)h0 * Wd + w0;
    long i01 = (long)h0 * Wd + w1;
    long i10 = (long)h1 * Wd + w0;
    long i11 = (long)h1 * Wd + w1;

#pragma unroll
    for (int c = 0; c < Cn; c++) {
        const float* p0 = data + (((long)b * Dn + d0) * Cn + c) * HWn;
        const float* p1 = data + (((long)b * Dn + d1) * Cn + c) * HWn;
        float v = w000 * p0[i00] + w001 * p0[i01]
                + w010 * p0[i10] + w011 * p0[i11]
                + w100 * p1[i00] + w101 * p1[i01]
                + w110 * p1[i10] + w111 * p1[i11];
        samp[(((long)b * Sn + s) * Cn + c) * HWn + hw] = v;
    }
}

// ---------------------------------------------------------------------------
// Final kernel-prediction combine: res_i[B,3,3,H,W], out[B,3,H,W]
// ---------------------------------------------------------------------------
__global__ void combine_k(const float* __restrict__ samp,
                          const float* __restrict__ wts,
                          float* __restrict__ res_i,
                          float* __restrict__ outp)
{
    long idx = blockIdx.x * 256L + threadIdx.x;      // over B*HW
    if (idx >= (long)Bn * HWn) return;
    int hw = (int)(idx % HWn);
    int b  = (int)(idx / HWn);

    float wv[Sn];
#pragma unroll
    for (int s = 0; s < Sn; s++)
        wv[s] = wts[((long)b * Sn + s) * HWn + hw];

    float o[3] = {0.f, 0.f, 0.f};
#pragma unroll
    for (int g = 0; g < 3; g++) {
#pragma unroll
        for (int c = 0; c < 3; c++) {
            float r = 0.f;
#pragma unroll
            for (int k = 0; k < 9; k++) {
                int s = g * 9 + k;
                r += samp[(((long)b * Sn + s) * Cn + c) * HWn + hw] * wv[s];
            }
            r *= 3.0f;
            res_i[(((long)b * 3 + g) * 3 + c) * HWn + hw] = r;
            o[c] += r;
        }
    }
#pragma unroll
    for (int c = 0; c < 3; c++)
        outp[((long)b * 3 + c) * HWn + hw] = o[c] * (1.0f / 3.0f);
}

// ---------------------------------------------------------------------------
extern "C" void kernel_launch(void* const* d_in, const int* in_sizes, int n_in,
                              void* d_out, int out_size)
{
    const float* data   = (const float*)d_in[0];
    const float* enc_w1 = (const float*)d_in[1];
    const float* enc_b1 = (const float*)d_in[2];
    const float* enc_w2 = (const float*)d_in[3];
    const float* enc_b2 = (const float*)d_in[4];
    const float* off_w  = (const float*)d_in[5];
    const float* off_b  = (const float*)d_in[6];
    const float* wc_w1  = (const float*)d_in[7];
    const float* wc_b1  = (const float*)d_in[8];
    const float* wc_w2  = (const float*)d_in[9];
    const float* wc_b2  = (const float*)d_in[10];
    const float* wc_w3  = (const float*)d_in[11];
    const float* wc_b3  = (const float*)d_in[12];
    float* out = (float*)d_out;

    float* f1;   cudaGetSymbolAddress((void**)&f1,   g_f1);
    float* feat; cudaGetSymbolAddress((void**)&feat, g_feat);
    float* offs; cudaGetSymbolAddress((void**)&offs, g_off);
    float* h1;   cudaGetSymbolAddress((void**)&h1,   g_h1);
    float* wt;   cudaGetSymbolAddress((void**)&wt,   g_wt);
    float* h2 = f1;  // reuse: f1 dead after feature is computed

    float* res_i = out + RES_OFF;
    float* outp  = out + OUT_OFF;
    float* samp  = out + SAMP_OFF;

    dim3 blk(256);
    const int BIG = 1 << 30;

    // 1) f1 = relu(conv(data 15 -> 64))
    {
        dim3 grid(Wd / 32, Hd / 32, Bn * (64 / 8));
        conv3x3_k<true><<<grid, blk>>>(data, BIG, (long)15 * HWn,
                                       nullptr, BIG, 0, nullptr, 0,
                                       enc_w1, enc_b1, f1, 15, 64);
    }
    // 2) feature = relu(conv(f1 64 -> 128))
    {
        dim3 grid(Wd / 32, Hd / 32, Bn * (128 / 8));
        conv3x3_k<true><<<grid, blk>>>(f1, BIG, (long)64 * HWn,
                                       nullptr, BIG, 0, nullptr, 0,
                                       enc_w2, enc_b2, feat, 64, 128);
    }
    // 3) offsets = conv(feature 128 -> 81)
    {
        dim3 grid(Wd / 32, Hd / 32, Bn * ((81 + 7) / 8));
        conv3x3_k<false><<<grid, blk>>>(feat, BIG, (long)128 * HWn,
                                        nullptr, BIG, 0, nullptr, 0,
                                        off_w, off_b, offs, 128, 81);
    }
    // 4) samples = trilinear(data, offsets)  -> d_out samples slice
    {
        long n = (long)Bn * Sn * HWn;
        trilerp_k<<<(unsigned)((n + 255) / 256), blk>>>(data, offs, samp);
    }
    // 5) h1 = relu(conv(concat[data(15), feature(128), samples(81)] -> 64))
    {
        dim3 grid(Wd / 32, Hd / 32, Bn * (64 / 8));
        conv3x3_k<true><<<grid, blk>>>(data, 15, (long)15 * HWn,
                                       feat, 143, (long)128 * HWn,
                                       samp, (long)81 * HWn,
                                       wc_w1, wc_b1, h1, 224, 64);
    }
    // 6) h2 = relu(conv(h1 64 -> 64))
    {
        dim3 grid(Wd / 32, Hd / 32, Bn * (64 / 8));
        conv3x3_k<true><<<grid, blk>>>(h1, BIG, (long)64 * HWn,
                                       nullptr, BIG, 0, nullptr, 0,
                                       wc_w2, wc_b2, h2, 64, 64);
    }
    // 7) weights = conv(h2 64 -> 27)
    {
        dim3 grid(Wd / 32, Hd / 32, Bn * ((27 + 7) / 8));
        conv3x3_k<false><<<grid, blk>>>(h2, BIG, (long)64 * HWn,
                                        nullptr, BIG, 0, nullptr, 0,
                                        wc_w3, wc_b3, wt, 64, 27);
    }
    // 8) res_i + out
    {
        long n = (long)Bn * HWn;
        combine_k<<<(unsigned)((n + 255) / 256), blk>>>(samp, wt, res_i, outp);
    }
}